// round 10
// baseline (speedup 1.0000x reference)
#include <cuda_runtime.h>
#include <cuda_bf16.h>
#include <cuda_fp16.h>
#include <math.h>
#include <stdint.h>

#define N_NODES 50000
#define N_EDGES 800000
#define IN_F 256
#define H_F 128
#define N_CLS 16
#define NBLK ((N_NODES + 255) / 256)   // 196
#define NPW 8                          // nodes per warp in agg1

// ---------------- device scratch ----------------
__device__ int      g_deg_in[N_NODES];
__device__ int      g_deg_out[N_NODES];
__device__ int      g_row_off[N_NODES + 1];
__device__ int      g_blk_sum[NBLK];
__device__ int      g_slot[N_EDGES];
__device__ int      g_edge_src[N_EDGES];
__device__ float    g_norm_in[N_NODES];
__device__ float    g_norm_out[N_NODES];
__device__ __half   g_feat_h[N_NODES * IN_F];   // fp16 copy of feat
__device__ __half   g_w1h_t[H_F * IN_F];        // W1 transposed [c][k], fp16
__device__ __half   g_x1h[N_NODES * H_F];
__device__ float    g_x2[N_NODES * N_CLS];
__device__ unsigned g_bar_cnt;

// ---------------- conversions (no dependencies) ----------------
__global__ void feat2h_kernel(const float* __restrict__ feat) {
    int i = blockIdx.x * 256 + threadIdx.x;          // one float4 each
    if (i >= N_NODES * IN_F / 4) return;
    float4 f = reinterpret_cast<const float4*>(feat)[i];
    __half2 a = __floats2half2_rn(f.x, f.y);
    __half2 b = __floats2half2_rn(f.z, f.w);
    uint2 u;
    *reinterpret_cast<__half2*>(&u.x) = a;
    *reinterpret_cast<__half2*>(&u.y) = b;
    reinterpret_cast<uint2*>(g_feat_h)[i] = u;
}

__global__ void w1t_kernel(const float* __restrict__ W1) {
    int i = blockIdx.x * 256 + threadIdx.x;          // 32768
    if (i >= IN_F * H_F) return;
    int k = i >> 7, c = i & 127;
    g_w1h_t[c * IN_F + k] = __float2half_rn(W1[i]);
}

// ---------------- setup ----------------
__global__ void zero_kernel() {
    int i = blockIdx.x * blockDim.x + threadIdx.x;
    if (i < N_NODES) { g_deg_in[i] = 0; g_deg_out[i] = 0; }
}

__global__ void deg_kernel(const int* __restrict__ src, const int* __restrict__ dst) {
    int e = blockIdx.x * blockDim.x + threadIdx.x;
    if (e >= N_EDGES) return;
    atomicAdd(&g_deg_out[src[e]], 1);
    g_slot[e] = atomicAdd(&g_deg_in[dst[e]], 1);
}

__global__ void norm_kernel() {
    int i = blockIdx.x * blockDim.x + threadIdx.x;
    if (i >= N_NODES) return;
    int di = g_deg_in[i], dd = g_deg_out[i];
    g_norm_in[i]  = di > 0 ? rsqrtf((float)di) : 0.f;
    g_norm_out[i] = dd > 0 ? rsqrtf((float)dd) : 0.f;
}

__global__ void scan_kernel() {
    __shared__ int sw[8];
    __shared__ int s_carry;
    int b = blockIdx.x, t = threadIdx.x, lane = t & 31, wid = t >> 5;
    int i = b * 256 + t;

    int v = (i < N_NODES) ? g_deg_in[i] : 0;
    int s = v;
    #pragma unroll
    for (int o = 16; o > 0; o >>= 1) s += __shfl_xor_sync(0xffffffffu, s, o);
    if (lane == 0) sw[wid] = s;
    __syncthreads();
    if (t == 0) {
        int tot = 0;
        #pragma unroll
        for (int j = 0; j < 8; j++) tot += sw[j];
        g_blk_sum[b] = tot;
        __threadfence();
        unsigned old = atomicAdd(&g_bar_cnt, 1u);
        unsigned target = (old / NBLK + 1u) * NBLK;
        volatile unsigned* p = &g_bar_cnt;
        while (*p < target) { }
    }
    __syncthreads();
    __threadfence();

    int cv = (t < NBLK && t < b) ? g_blk_sum[t] : 0;
    #pragma unroll
    for (int o = 16; o > 0; o >>= 1) cv += __shfl_xor_sync(0xffffffffu, cv, o);
    __syncthreads();
    if (lane == 0) sw[wid] = cv;
    __syncthreads();
    if (t == 0) {
        int tot = 0;
        #pragma unroll
        for (int j = 0; j < 8; j++) tot += sw[j];
        s_carry = tot;
    }
    __syncthreads();
    int carry = s_carry;
    __syncthreads();

    int x = v;
    #pragma unroll
    for (int o = 1; o < 32; o <<= 1) {
        int y = __shfl_up_sync(0xffffffffu, x, o);
        if (lane >= o) x += y;
    }
    if (lane == 31) sw[wid] = x;
    __syncthreads();
    if (wid == 0 && lane < 8) {
        int ss = sw[lane];
        #pragma unroll
        for (int o = 1; o < 8; o <<= 1) {
            int y = __shfl_up_sync(0xffu, ss, o);
            if (lane >= o) ss += y;
        }
        sw[lane] = ss;
    }
    __syncthreads();
    int excl = carry + (wid ? sw[wid - 1] : 0) + x - v;
    if (i < N_NODES) g_row_off[i] = excl;
    if (i == N_NODES - 1) g_row_off[N_NODES] = excl + v;
}

__global__ void fill_kernel(const int* __restrict__ src, const int* __restrict__ dst) {
    int e = blockIdx.x * blockDim.x + threadIdx.x;
    if (e >= N_EDGES) return;
    g_edge_src[g_row_off[dst[e]] + g_slot[e]] = src[e];
}

// ---------------- GEMM1: fp16 m16n8k16 mma + cp.async ----------------
__device__ __forceinline__ void mma_f16(float* d, const uint32_t* a,
                                        uint32_t b0, uint32_t b1, const float* c) {
    asm volatile(
        "mma.sync.aligned.m16n8k16.row.col.f32.f16.f16.f32 "
        "{%0,%1,%2,%3}, {%4,%5,%6,%7}, {%8,%9}, {%10,%11,%12,%13};\n"
        : "=f"(d[0]), "=f"(d[1]), "=f"(d[2]), "=f"(d[3])
        : "r"(a[0]), "r"(a[1]), "r"(a[2]), "r"(a[3]),
          "r"(b0), "r"(b1),
          "f"(c[0]), "f"(c[1]), "f"(c[2]), "f"(c[3]));
}
__device__ __forceinline__ void cp16(uint32_t saddr, const void* gptr) {
    asm volatile("cp.async.cg.shared.global [%0], [%1], 16;\n" :: "r"(saddr), "l"(gptr));
}
__device__ __forceinline__ void cp_commit() {
    asm volatile("cp.async.commit_group;\n" ::: "memory");
}
__device__ __forceinline__ void cp_wait1() {
    asm volatile("cp.async.wait_group 1;\n" ::: "memory");
}

#define KC 64
#define AST 72                        // halves; (36w + t) % 32 conflict-free
#define ABUF (128 * AST)              // halves per buffer
#define GEMM1_SMEM (2 * (ABUF + ABUF) * 2)   // 73728 B

__global__ void __launch_bounds__(256) gemm1_kernel() {
    extern __shared__ __half smem_h[];
    __half* sA = smem_h;               // [2][ABUF]
    __half* sB = smem_h + 2 * ABUF;    // [2][ABUF]

    int t = threadIdx.x;
    int lane = t & 31, wid = t >> 5;
    int wm = wid >> 1, wn = wid & 1;   // warp tile: rows wm*32, cols wn*64
    int row0 = blockIdx.x * 128;
    int g = lane >> 2, tg = lane & 3;

    float acc[2][8][4];
    #pragma unroll
    for (int mt = 0; mt < 2; mt++)
        #pragma unroll
        for (int nt = 0; nt < 8; nt++)
            #pragma unroll
            for (int q = 0; q < 4; q++) acc[mt][nt][q] = 0.f;

    // staging: 4 × 16B pieces each for A and B
    int prow[4], ppc[4], gr[4];
    uint32_t saA[4], saB[4];
    #pragma unroll
    for (int j = 0; j < 4; j++) {
        int idx = t + j * 256;         // 0..1023 = 128 rows × 8 pieces
        prow[j] = idx >> 3; ppc[j] = idx & 7;
        saA[j] = (uint32_t)__cvta_generic_to_shared(&sA[prow[j] * AST + ppc[j] * 8]);
        saB[j] = (uint32_t)__cvta_generic_to_shared(&sB[prow[j] * AST + ppc[j] * 8]);
        int grow = row0 + prow[j];
        gr[j] = grow < N_NODES ? grow : N_NODES - 1;
    }

    #pragma unroll
    for (int j = 0; j < 4; j++) {
        cp16(saA[j], g_feat_h + gr[j] * IN_F + ppc[j] * 8);
        cp16(saB[j], g_w1h_t + prow[j] * IN_F + ppc[j] * 8);
    }
    cp_commit();

    for (int kc = 0; kc < 4; kc++) {
        int cur = kc & 1;
        if (kc < 3) {
            uint32_t off = (uint32_t)((cur ^ 1) * ABUF * 2);
            #pragma unroll
            for (int j = 0; j < 4; j++) {
                cp16(saA[j] + off, g_feat_h + gr[j] * IN_F + (kc + 1) * KC + ppc[j] * 8);
                cp16(saB[j] + off, g_w1h_t + prow[j] * IN_F + (kc + 1) * KC + ppc[j] * 8);
            }
            cp_commit();
        } else {
            cp_commit();
        }
        cp_wait1();
        __syncthreads();

        __half* cA = sA + cur * ABUF;
        __half* cB = sB + cur * ABUF;
        #pragma unroll
        for (int ks = 0; ks < 4; ks++) {
            int k0 = ks * 16;
            uint32_t a[2][4];
            #pragma unroll
            for (int mt = 0; mt < 2; mt++) {
                int r = wm * 32 + mt * 16 + g;
                a[mt][0] = *reinterpret_cast<uint32_t*>(&cA[r * AST + k0 + 2 * tg]);
                a[mt][1] = *reinterpret_cast<uint32_t*>(&cA[(r + 8) * AST + k0 + 2 * tg]);
                a[mt][2] = *reinterpret_cast<uint32_t*>(&cA[r * AST + k0 + 8 + 2 * tg]);
                a[mt][3] = *reinterpret_cast<uint32_t*>(&cA[(r + 8) * AST + k0 + 8 + 2 * tg]);
            }
            #pragma unroll
            for (int nt = 0; nt < 8; nt++) {
                int n = wn * 64 + nt * 8 + g;
                uint32_t b0 = *reinterpret_cast<uint32_t*>(&cB[n * AST + k0 + 2 * tg]);
                uint32_t b1 = *reinterpret_cast<uint32_t*>(&cB[n * AST + k0 + 8 + 2 * tg]);
                mma_f16(acc[0][nt], a[0], b0, b1, acc[0][nt]);
                mma_f16(acc[1][nt], a[1], b0, b1, acc[1][nt]);
            }
        }
        __syncthreads();
    }

    #pragma unroll
    for (int mt = 0; mt < 2; mt++) {
        int r  = row0 + wm * 32 + mt * 16 + g;
        int r2 = r + 8;
        float no1 = (r  < N_NODES) ? g_norm_out[r]  : 0.f;
        float no2 = (r2 < N_NODES) ? g_norm_out[r2] : 0.f;
        #pragma unroll
        for (int nt = 0; nt < 8; nt++) {
            int col = wn * 64 + nt * 8 + tg * 2;
            if (r < N_NODES)
                *reinterpret_cast<__half2*>(&g_x1h[r * H_F + col]) =
                    __floats2half2_rn(acc[mt][nt][0] * no1, acc[mt][nt][1] * no1);
            if (r2 < N_NODES)
                *reinterpret_cast<__half2*>(&g_x1h[r2 * H_F + col]) =
                    __floats2half2_rn(acc[mt][nt][2] * no2, acc[mt][nt][3] * no2);
        }
    }
}

// ---------------- fused Agg1 + ReLU + GEMM2: half-warp per edge, LDG.128 ----------------
__global__ void __launch_bounds__(256) agg1_gemm2_kernel(const float* __restrict__ b1,
                                                         const float* __restrict__ W2) {
    __shared__ float sWt[N_CLS * H_F];   // transposed [c][k]
    for (int i = threadIdx.x; i < H_F * N_CLS; i += 256) {
        int k = i >> 4, c = i & 15;
        sWt[c * H_F + k] = W2[i];
    }
    __syncthreads();

    int warp = threadIdx.x >> 5, lane = threadIdx.x & 31;
    int hw = lane >> 4, cl = lane & 15;          // half-warp id, lane-in-half
    int node0 = (blockIdx.x * 8 + warp) * NPW;
    const uint4* x1q = reinterpret_cast<const uint4*>(g_x1h);  // row stride 16

    // lane covers cols [8*cl, 8*cl+8)
    float4 b1a = reinterpret_cast<const float4*>(b1)[2 * cl];
    float4 b1b = reinterpret_cast<const float4*>(b1)[2 * cl + 1];

    #define ACC8(u) do {                                                      \
        float2 f0 = __half22float2(*reinterpret_cast<__half2*>(&(u).x));      \
        float2 f1 = __half22float2(*reinterpret_cast<__half2*>(&(u).y));      \
        float2 f2 = __half22float2(*reinterpret_cast<__half2*>(&(u).z));      \
        float2 f3 = __half22float2(*reinterpret_cast<__half2*>(&(u).w));      \
        acc[0] += f0.x; acc[1] += f0.y; acc[2] += f1.x; acc[3] += f1.y;       \
        acc[4] += f2.x; acc[5] += f2.y; acc[6] += f3.x; acc[7] += f3.y;       \
    } while (0)

    #pragma unroll 1
    for (int it = 0; it < NPW; it++) {
        int node = node0 + it;
        if (node >= N_NODES) break;
        int beg = g_row_off[node], end = g_row_off[node + 1];
        int deg = end - beg;

        int v0 = (beg + lane      < end) ? g_edge_src[beg + lane]      : 0;
        int v1 = (beg + 32 + lane < end) ? g_edge_src[beg + 32 + lane] : 0;

        float acc[8];
        #pragma unroll
        for (int q = 0; q < 8; q++) acc[q] = 0.f;

        // batch 0: edges [0, d0); this half handles indices j+hw (stride 2)
        int d0 = deg < 32 ? deg : 32;
        for (int j = 0; j < d0; j += 4) {
            int i0 = j + hw, i1 = j + 2 + hw;
            int s0 = __shfl_sync(0xffffffffu, v0, i0 & 31);
            int s1 = __shfl_sync(0xffffffffu, v0, i1 & 31);
            if (i0 < d0) { uint4 u = x1q[s0 * 16 + cl]; ACC8(u); }
            if (i1 < d0) { uint4 u = x1q[s1 * 16 + cl]; ACC8(u); }
        }
        if (deg > 32) {
            int d1 = deg - 32; if (d1 > 32) d1 = 32;
            for (int j = 0; j < d1; j += 4) {
                int i0 = j + hw, i1 = j + 2 + hw;
                int s0 = __shfl_sync(0xffffffffu, v1, i0 & 31);
                int s1 = __shfl_sync(0xffffffffu, v1, i1 & 31);
                if (i0 < d1) { uint4 u = x1q[s0 * 16 + cl]; ACC8(u); }
                if (i1 < d1) { uint4 u = x1q[s1 * 16 + cl]; ACC8(u); }
            }
            for (int e = beg + 64 + hw; e < end; e += 2) {   // rare tail
                int s = g_edge_src[e];
                uint4 u = x1q[s * 16 + cl]; ACC8(u);
            }
        }

        // combine the two halves (cols identical, edges disjoint)
        #pragma unroll
        for (int q = 0; q < 8; q++)
            acc[q] += __shfl_xor_sync(0xffffffffu, acc[q], 16);

        float ni = g_norm_in[node], no = g_norm_out[node];
        float h[8];
        h[0] = fmaxf(fmaf(acc[0], ni, b1a.x), 0.f) * no;
        h[1] = fmaxf(fmaf(acc[1], ni, b1a.y), 0.f) * no;
        h[2] = fmaxf(fmaf(acc[2], ni, b1a.z), 0.f) * no;
        h[3] = fmaxf(fmaf(acc[3], ni, b1a.w), 0.f) * no;
        h[4] = fmaxf(fmaf(acc[4], ni, b1b.x), 0.f) * no;
        h[5] = fmaxf(fmaf(acc[5], ni, b1b.y), 0.f) * no;
        h[6] = fmaxf(fmaf(acc[6], ni, b1b.z), 0.f) * no;
        h[7] = fmaxf(fmaf(acc[7], ni, b1b.w), 0.f) * no;

        // gemm2 split: half hw computes classes [hw*8, hw*8+8)
        float p[8];
        #pragma unroll
        for (int cc = 0; cc < 8; cc++) {
            int c = hw * 8 + cc;
            float4 wA = *reinterpret_cast<const float4*>(&sWt[c * H_F + 8 * cl]);
            float4 wB = *reinterpret_cast<const float4*>(&sWt[c * H_F + 8 * cl + 4]);
            p[cc] = fmaf(h[0], wA.x, fmaf(h[1], wA.y, fmaf(h[2], wA.z,
                    fmaf(h[3], wA.w, fmaf(h[4], wB.x, fmaf(h[5], wB.y,
                    fmaf(h[6], wB.z, h[7] * wB.w)))))));
        }
        unsigned hm = hw ? 0xFFFF0000u : 0x0000FFFFu;
        #pragma unroll
        for (int o = 8; o > 0; o >>= 1) {
            #pragma unroll
            for (int cc = 0; cc < 8; cc++)
                p[cc] += __shfl_xor_sync(hm, p[cc], o, 16);
        }
        if (cl < 8) {
            float outv = p[0];
            #pragma unroll
            for (int cc = 1; cc < 8; cc++) if (cl == cc) outv = p[cc];
            g_x2[node * N_CLS + hw * 8 + cl] = outv;
        }
    }
    #undef ACC8
}

// ---------------- Agg2 + bias + log_softmax ----------------
__global__ void __launch_bounds__(256) agg2_kernel(const float* __restrict__ b2,
                                                   float* __restrict__ out) {
    int node = blockIdx.x * 16 + (threadIdx.x >> 4);
    int c = threadIdx.x & 15;
    unsigned hm = 0xFFFFu << (((threadIdx.x >> 4) & 1) * 16);
    int beg = g_row_off[node], end = g_row_off[node + 1];
    int deg = end - beg;

    int v0 = (beg + c      < end) ? g_edge_src[beg + c]      : 0;
    int v1 = (beg + 16 + c < end) ? g_edge_src[beg + 16 + c] : 0;
    int v2 = (beg + 32 + c < end) ? g_edge_src[beg + 32 + c] : 0;
    int v3 = (beg + 48 + c < end) ? g_edge_src[beg + 48 + c] : 0;

    float acc = 0.f;
    int dcap = deg < 64 ? deg : 64;
    for (int j = 0; j < dcap; j++) {
        int w = j >> 4, jj = j & 15;
        int s = __shfl_sync(hm, w == 0 ? v0 : w == 1 ? v1 : w == 2 ? v2 : v3, jj, 16);
        acc += g_x2[s * N_CLS + c];
    }
    for (int e = beg + 64; e < end; e++)
        acc += g_x2[g_edge_src[e] * N_CLS + c];

    float v = fmaf(acc, g_norm_in[node], b2[c]);
    float m = v;
    #pragma unroll
    for (int o = 8; o > 0; o >>= 1)
        m = fmaxf(m, __shfl_xor_sync(hm, m, o, 16));
    float e = expf(v - m);
    float s = e;
    #pragma unroll
    for (int o = 8; o > 0; o >>= 1)
        s += __shfl_xor_sync(hm, s, o, 16);
    out[node * N_CLS + c] = v - m - logf(s);
}

// ---------------- launch (fork/join graph) ----------------
extern "C" void kernel_launch(void* const* d_in, const int* in_sizes, int n_in,
                              void* d_out, int out_size) {
    const float* feat = (const float*)d_in[0];
    const int*   src  = (const int*)  d_in[1];
    const int*   dst  = (const int*)  d_in[2];
    const float* W1   = (const float*)d_in[3];
    const float* b1   = (const float*)d_in[4];
    const float* W2   = (const float*)d_in[5];
    const float* b2   = (const float*)d_in[6];
    float* out = (float*)d_out;
    (void)in_sizes; (void)n_in; (void)out_size;

    static cudaStream_t s2 = nullptr;
    static cudaEvent_t evFork = nullptr, evNorm = nullptr, evJoin = nullptr;
    if (s2 == nullptr) {
        cudaStreamCreateWithFlags(&s2, cudaStreamNonBlocking);
        cudaEventCreateWithFlags(&evFork, cudaEventDisableTiming);
        cudaEventCreateWithFlags(&evNorm, cudaEventDisableTiming);
        cudaEventCreateWithFlags(&evJoin, cudaEventDisableTiming);
        cudaFuncSetAttribute(gemm1_kernel, cudaFuncAttributeMaxDynamicSharedMemorySize,
                             GEMM1_SMEM);
    }

    // fork immediately: conversions have no dependencies
    cudaEventRecord(evFork, 0);
    cudaStreamWaitEvent(s2, evFork, 0);
    feat2h_kernel<<<N_NODES * IN_F / 4 / 256, 256, 0, s2>>>(feat);
    w1t_kernel<<<(IN_F * H_F + 255) / 256, 256, 0, s2>>>(W1);

    // main: degrees + norms
    zero_kernel<<<(N_NODES + 255) / 256, 256>>>();
    deg_kernel<<<(N_EDGES + 255) / 256, 256>>>(src, dst);
    norm_kernel<<<(N_NODES + 255) / 256, 256>>>();

    // gemm1 (s2) needs norms; runs parallel to scan+fill
    cudaEventRecord(evNorm, 0);
    cudaStreamWaitEvent(s2, evNorm, 0);
    gemm1_kernel<<<(N_NODES + 127) / 128, 256, GEMM1_SMEM, s2>>>();
    scan_kernel<<<NBLK, 256>>>();
    fill_kernel<<<(N_EDGES + 255) / 256, 256>>>(src, dst);
    cudaEventRecord(evJoin, s2);
    cudaStreamWaitEvent(0, evJoin, 0);

    agg1_gemm2_kernel<<<(N_NODES + 8 * NPW * 8 - 1) / (8 * NPW), 256>>>(b1, W2);
    agg2_kernel<<<N_NODES / 16, 256>>>(b2, out);
}